// round 2
// baseline (speedup 1.0000x reference)
#include <cuda_runtime.h>

#define NPTS 16000
#define GPT  2000
#define CIN  128
#define COUT 128
#define DX   400
#define DY   400
#define DZ   31          // fp32: (0.9f-(-2.3f))/0.1f = 31.9999... -> 31
#define KC   62

#define HBITS 16
#define HSIZE (1 << HBITS)
#define HMASK (HSIZE - 1)

#define BM   128
#define PCAP 512

typedef unsigned long long u64;

// ---- scratch (device globals; allocations are forbidden) ----
__device__ uint2 g_tab[HSIZE];     // {key, val}
__device__ int   g_pidx[NPTS];     // packed voxel idx per point

__device__ __forceinline__ unsigned int hash_key(unsigned int key) {
    return (key * 2654435761u) >> (32 - HBITS);
}

__device__ __forceinline__ u64 ffma2(u64 a, u64 b, u64 c) {
    u64 d;
    asm("fma.rn.f32x2 %0, %1, %2, %3;" : "=l"(d) : "l"(a), "l"(b), "l"(c));
    return d;
}

// ---------------------------------------------------------------------------
__global__ void k_clear() {
    int t = blockIdx.x * blockDim.x + threadIdx.x;
    g_tab[t] = make_uint2(0u, 0u);
}

// ---------------------------------------------------------------------------
// Replicates: xyz = a*(hi-lo)+lo ; idx = (int)((xyz-lo)/0.1f)  (fp32, no fma)
__global__ void k_insert(const float* __restrict__ anchor) {
    int i = blockIdx.x * blockDim.x + threadIdx.x;
    if (i >= NPTS) return;

    float ax = anchor[3 * i + 0];
    float ay = anchor[3 * i + 1];
    float az = anchor[3 * i + 2];

    const float lox = -20.0f, loy = -20.0f, loz = -2.3f;
    const float step = 0.1f;

    float xx = __fadd_rn(__fmul_rn(ax, 40.0f), lox);
    float yy = __fadd_rn(__fmul_rn(ay, 40.0f), loy);
    float zz = __fadd_rn(__fmul_rn(az, __fsub_rn(0.9f, -2.3f)), loz);

    int ix = (int)__fdiv_rn(__fsub_rn(xx, lox), step);
    int iy = (int)__fdiv_rn(__fsub_rn(yy, loy), step);
    int iz = (int)__fdiv_rn(__fsub_rn(zz, loz), step);

    g_pidx[i] = (ix << 14) | (iy << 5) | iz;   // ix:9b iy:9b iz:5b

    if (ix >= 0 && ix < DX && iy >= 0 && iy < DY && iz >= 0 && iz < DZ) {
        int b = i / GPT;
        unsigned int key = 1u + (unsigned int)((((b * DX + ix) * DY + iy) * DZ) + iz);
        unsigned int h = hash_key(key);
        while (true) {
            unsigned int old = atomicCAS(&g_tab[h].x, 0u, key);
            if (old == 0u || old == key) {
                atomicMax(&g_tab[h].y, (unsigned int)(i + 1));  // last-wins == max idx
                break;
            }
            h = (h + 1) & HMASK;
        }
    }
}

// ---------------------------------------------------------------------------
__device__ __forceinline__ int resolve(uint2 e, unsigned int key, unsigned int h) {
    while (e.x != 0u && e.x != key) {       // rare collision walk
        h = (h + 1) & HMASK;
        e = g_tab[h];
    }
    return (e.x == key) ? (int)e.y - 1 : -1;
}

// smem layout (floats):
//   [0, 32768)          As_dup : 128 k x 256 (each A value duplicated)
//   [32768, 49152)      Bs     : 128 k x 128
//   then ints: jc[128], pidx[128], pcnt, pairs[PCAP*3]
#define A_OFF 0
#define B_OFF 32768
#define I_OFF 49152
#define SMEM_FLOATS (I_OFF + 128 + 128 + 8 + PCAP * 3)

__global__ void __launch_bounds__(256, 1)
k_gemm(const float* __restrict__ feats, const float* __restrict__ w,
       float* __restrict__ out) {
    extern __shared__ float smem[];
    int*  jc_s   = (int*)(smem + I_OFF);
    int*  pidx_s = jc_s + 128;
    int*  pcnt   = pidx_s + 128;
    int*  pairs  = pcnt + 8;

    const int tid = threadIdx.x;              // 256
    const int rowbase = blockIdx.x * BM;
    const float* w62 = w + KC * CIN * COUT;

    // ---- phase 0: center lookups ----
    if (tid == 0) *pcnt = 0;
    if (tid < BM) {
        int p = g_pidx[rowbase + tid];
        pidx_s[tid] = p;
        int ix = p >> 14, iy = (p >> 5) & 0x1FF, iz = p & 0x1F;
        int j = -1;
        if (ix < DX && iy < DY && iz < DZ) {   // packed coords are >= 0
            int b = (rowbase + tid) / GPT;
            unsigned int key = 1u + (unsigned int)((((b * DX + ix) * DY + iy) * DZ) + iz);
            unsigned int h = hash_key(key);
            j = resolve(g_tab[h], key, h);
        }
        jc_s[tid] = j;
    }
    __syncthreads();

    // ---- phase 1a: neighbor probes (124 non-center offsets x 128 rows) ----
    {
        const int NQ = BM * 124;               // 15872
        for (int c0 = 0; c0 < 64; c0 += 4) {
            unsigned int key[4], h[4];
            uint2 e[4];
            int   rr[4], kr[4];
            bool  act[4];
#pragma unroll
            for (int u = 0; u < 4; u++) {
                int q = tid + (c0 + u) * 256;
                act[u] = (q < NQ);
                int r  = q & (BM - 1);
                int kk = q >> 7;                // 0..123
                int k_real = kk + (kk >= KC);   // skip center
                rr[u] = r; kr[u] = k_real;
                int p  = pidx_s[r];
                int nx = (p >> 14) + k_real / 25 - 2;
                int ny = ((p >> 5) & 0x1FF) + (k_real / 5) % 5 - 2;
                int nz = (p & 0x1F) + k_real % 5 - 2;
                bool inb = act[u] && nx >= 0 && nx < DX && ny >= 0 && ny < DY &&
                           nz >= 0 && nz < DZ;
                act[u] = inb;
                if (inb) {
                    int b = (rowbase + r) / GPT;
                    key[u] = 1u + (unsigned int)((((b * DX + nx) * DY + ny) * DZ) + nz);
                    h[u]   = hash_key(key[u]);
                    e[u]   = g_tab[h[u]];       // batched independent loads (MLP=4)
                }
            }
#pragma unroll
            for (int u = 0; u < 4; u++) {
                if (act[u]) {
                    int j = resolve(e[u], key[u], h[u]);
                    if (j >= 0) {
                        int pos = atomicAdd(pcnt, 1);
                        if (pos < PCAP) {
                            pairs[3 * pos + 0] = rr[u];
                            pairs[3 * pos + 1] = kr[u];
                            pairs[3 * pos + 2] = j;
                        }
                    }
                }
            }
        }
    }

    // ---- phase 1b: fill As (gathered, duplicated) and Bs ----
#pragma unroll
    for (int it = 0; it < 16; it++) {
        int idx = tid + it * 256;               // 0..4095
        int r = idx & 127, cv = idx >> 7;       // cv: 0..31 (float4 col)
        int j = jc_s[r];
        float4 v = make_float4(0.f, 0.f, 0.f, 0.f);
        if (j >= 0) v = __ldg((const float4*)(feats + j * CIN) + cv);
        float* dst = smem + A_OFF + (4 * cv) * 256 + 2 * r;
        *(float2*)(dst + 0 * 256) = make_float2(v.x, v.x);
        *(float2*)(dst + 1 * 256) = make_float2(v.y, v.y);
        *(float2*)(dst + 2 * 256) = make_float2(v.z, v.z);
        *(float2*)(dst + 3 * 256) = make_float2(v.w, v.w);
    }
#pragma unroll
    for (int it = 0; it < 16; it++) {
        int idx = tid + it * 256;               // 0..4095
        int kk = idx >> 5, cv = idx & 31;
        ((float4*)(smem + B_OFF + kk * 128))[cv] =
            __ldg((const float4*)(w62 + kk * COUT) + cv);
    }
    __syncthreads();

    // ---- phase 2: main FFMA2 loop ----
    const int tx = tid & 15;                    // cols 8tx..8tx+7
    const int ty = tid >> 4;                    // rows 8ty..8ty+7
    u64 acc[8][4];
#pragma unroll
    for (int r = 0; r < 8; r++)
#pragma unroll
        for (int c = 0; c < 4; c++) acc[r][c] = 0ull;

    const float* Abase = smem + A_OFF + 16 * ty;
    const float* Bbase = smem + B_OFF + 8 * tx;
#pragma unroll 4
    for (int k = 0; k < CIN; k++) {
        ulonglong2 a01 = *(const ulonglong2*)(Abase + k * 256 + 0);
        ulonglong2 a23 = *(const ulonglong2*)(Abase + k * 256 + 4);
        ulonglong2 a45 = *(const ulonglong2*)(Abase + k * 256 + 8);
        ulonglong2 a67 = *(const ulonglong2*)(Abase + k * 256 + 12);
        ulonglong2 b01 = *(const ulonglong2*)(Bbase + k * 128 + 0);
        ulonglong2 b23 = *(const ulonglong2*)(Bbase + k * 128 + 4);
        u64 ad[8] = {a01.x, a01.y, a23.x, a23.y, a45.x, a45.y, a67.x, a67.y};
        u64 bd[4] = {b01.x, b01.y, b23.x, b23.y};
#pragma unroll
        for (int r = 0; r < 8; r++)
#pragma unroll
            for (int c = 0; c < 4; c++)
                acc[r][c] = ffma2(ad[r], bd[c], acc[r][c]);
    }

    // ---- phase 3: store main result ----
#pragma unroll
    for (int r = 0; r < 8; r++) {
        int row = rowbase + 8 * ty + r;
        float2 p0 = *(float2*)&acc[r][0];
        float2 p1 = *(float2*)&acc[r][1];
        float2 p2 = *(float2*)&acc[r][2];
        float2 p3 = *(float2*)&acc[r][3];
        float4* o = (float4*)(out + row * COUT + 8 * tx);
        o[0] = make_float4(p0.x, p0.y, p1.x, p1.y);
        o[1] = make_float4(p2.x, p2.y, p3.x, p3.y);
    }
    __syncthreads();

    // ---- phase 4: rare neighbor fixups (block owns its rows exclusively) ----
    int cnt = *pcnt;
    if (cnt > PCAP) cnt = PCAP;
    for (int p = 0; p < cnt; p++) {
        int rl = pairs[3 * p + 0];
        int kk = pairs[3 * p + 1];
        int j  = pairs[3 * p + 2];
        if (tid < COUT) {
            const float* f  = feats + j * CIN;
            const float* wk = w + kk * CIN * COUT;
            float s = 0.0f;
#pragma unroll 8
            for (int c = 0; c < CIN; c++)
                s += __ldg(f + c) * __ldg(wk + c * COUT + tid);
            out[(rowbase + rl) * COUT + tid] += s;   // same thread/col per row: no race
        }
    }
}

// ---------------------------------------------------------------------------
extern "C" void kernel_launch(void* const* d_in, const int* in_sizes, int n_in,
                              void* d_out, int out_size) {
    const float* feats  = (const float*)d_in[0];
    const float* anchor = (const float*)d_in[1];
    const float* w      = (const float*)d_in[2];
    float* out = (float*)d_out;

    static_assert(SMEM_FLOATS * 4 < 230000, "smem");
    cudaFuncSetAttribute(k_gemm, cudaFuncAttributeMaxDynamicSharedMemorySize,
                         SMEM_FLOATS * 4);

    k_clear<<<HSIZE / 256, 256>>>();
    k_insert<<<(NPTS + 255) / 256, 256>>>(anchor);
    k_gemm<<<NPTS / BM, 256, SMEM_FLOATS * 4>>>(feats, w, out);
}

// round 3
// speedup vs baseline: 1.9736x; 1.9736x over previous
#include <cuda_runtime.h>

#define NPTS 16000
#define GPT  2000
#define CIN  128
#define COUT 128
#define DX   400
#define DY   400
#define DZ   31          // fp32: (0.9f-(-2.3f))/0.1f = 31.9999... -> 31
#define KC   62

#define HBITS 16
#define HSIZE (1 << HBITS)
#define HMASK (HSIZE - 1)
#define MAXP  (1 << 16)
#define NCOL  (8 * DX * DY)

typedef unsigned long long u64;

// ---- scratch (device globals; allocations are forbidden) ----
__device__ uint2        g_tab[HSIZE];      // {key, val}
__device__ unsigned int g_colmask[NCOL];   // z-occupancy bitmap per (b,x,y)
__device__ int          g_pidx[NPTS];
__device__ int          g_jc[NPTS];
__device__ int          g_pairs[3 * MAXP];
__device__ int          g_paircnt;

__device__ __forceinline__ unsigned int hash_key(unsigned int key) {
    return (key * 2654435761u) >> (32 - HBITS);
}

__device__ __forceinline__ u64 ffma2(u64 a, u64 b, u64 c) {
    u64 d;
    asm("fma.rn.f32x2 %0, %1, %2, %3;" : "=l"(d) : "l"(a), "l"(b), "l"(c));
    return d;
}

// ---------------------------------------------------------------------------
__global__ void k_clear() {
    int t = blockIdx.x * blockDim.x + threadIdx.x;   // 320000 threads
    if (t < HSIZE) g_tab[t] = make_uint2(0u, 0u);
    // colmask: 1,280,000 words = 320,000 uint4
    ((uint4*)g_colmask)[t] = make_uint4(0u, 0u, 0u, 0u);
    if (t == 0) g_paircnt = 0;
}

// ---------------------------------------------------------------------------
// Replicates: xyz = a*(hi-lo)+lo ; idx = (int)((xyz-lo)/0.1f)  (fp32, no fma)
__global__ void k_insert(const float* __restrict__ anchor) {
    int i = blockIdx.x * blockDim.x + threadIdx.x;
    if (i >= NPTS) return;

    float ax = anchor[3 * i + 0];
    float ay = anchor[3 * i + 1];
    float az = anchor[3 * i + 2];

    const float lox = -20.0f, loy = -20.0f, loz = -2.3f;
    const float step = 0.1f;

    float xx = __fadd_rn(__fmul_rn(ax, 40.0f), lox);
    float yy = __fadd_rn(__fmul_rn(ay, 40.0f), loy);
    float zz = __fadd_rn(__fmul_rn(az, __fsub_rn(0.9f, -2.3f)), loz);

    int ix = (int)__fdiv_rn(__fsub_rn(xx, lox), step);
    int iy = (int)__fdiv_rn(__fsub_rn(yy, loy), step);
    int iz = (int)__fdiv_rn(__fsub_rn(zz, loz), step);

    g_pidx[i] = (ix << 14) | (iy << 5) | iz;   // ix:9b iy:9b iz:5b (iz<=31)
    g_jc[i] = -1;

    if (ix < DX && iy < DY && iz < DZ) {       // coords are >= 0 by construction
        int b = i / GPT;
        unsigned int key = 1u + (unsigned int)((((b * DX + ix) * DY + iy) * DZ) + iz);
        unsigned int h = hash_key(key);
        while (true) {
            unsigned int old = atomicCAS(&g_tab[h].x, 0u, key);
            if (old == 0u || old == key) {
                atomicMax(&g_tab[h].y, (unsigned int)(i + 1));  // last-wins
                break;
            }
            h = (h + 1) & HMASK;
        }
        atomicOr(&g_colmask[(b * DX + ix) * DY + iy], 1u << iz);
    }
}

// ---------------------------------------------------------------------------
__device__ __forceinline__ int hash_lookup(int b, int nx, int ny, int nz) {
    unsigned int key = 1u + (unsigned int)((((b * DX + nx) * DY + ny) * DZ) + nz);
    unsigned int h = hash_key(key);
    while (true) {
        uint2 e = g_tab[h];
        if (e.x == key) return (int)e.y - 1;
        if (e.x == 0u)  return -1;
        h = (h + 1) & HMASK;
    }
}

// one thread per (point, x/y-offset): 16000 x 25 (padded to 32)
__global__ void k_pairs() {
    int t = blockIdx.x * blockDim.x + threadIdx.x;
    int i = t >> 5;
    int c = t & 31;
    if (i >= NPTS || c >= 25) return;

    int p  = g_pidx[i];
    int ix = p >> 14, iy = (p >> 5) & 0x1FF, iz = p & 0x1F;
    int dx = c / 5 - 2;
    int dy = c % 5 - 2;
    int nx = ix + dx, ny = iy + dy;
    if (nx < 0 || nx >= DX || ny < 0 || ny >= DY) return;

    int b = i / GPT;
    unsigned int bits = g_colmask[(b * DX + nx) * DY + ny];
    int lo = iz - 2;
    unsigned int wnd = (lo >= 0) ? (0x1Fu << lo) : (0x1Fu >> -lo);
    bits &= wnd;

    while (bits) {
        int nz = __ffs(bits) - 1;
        bits &= bits - 1;
        int j = hash_lookup(b, nx, ny, nz);          // bit set => found
        int k = (dx + 2) * 25 + (dy + 2) * 5 + (nz - iz + 2);
        if (k == KC) {
            g_jc[i] = j;
        } else if (j >= 0) {
            int pos = atomicAdd(&g_paircnt, 1);
            if (pos < MAXP) {
                g_pairs[3 * pos + 0] = i;
                g_pairs[3 * pos + 1] = k;
                g_pairs[3 * pos + 2] = j;
            }
        }
    }
}

// ---------------------------------------------------------------------------
// FFMA2 GEMM: out[rowbase..rowbase+63][:] = feats[jc[row]] @ w[62]
// BM=64, 128 threads, k-tile 64. A duplicated in smem -> (a,a) pairs,
// B natural -> (b_c, b_{c+1}) pairs; acc holds column pairs.
#define KT 64
#define GEMM_SMEM (2 * KT * 128 * 4 + 64 * 4)

__global__ void __launch_bounds__(128, 2)
k_gemm(const float* __restrict__ feats, const float* __restrict__ w,
       float* __restrict__ out) {
    extern __shared__ float sm[];
    float* As  = sm;                    // [KT][128]: col 2r,2r+1 = dup of row r
    float* Bs  = sm + KT * 128;         // [KT][128]
    int*  jrow = (int*)(sm + 2 * KT * 128);

    const int tid = threadIdx.x;        // 128
    const int tx = tid & 15;            // cols 8tx .. 8tx+7
    const int ty = tid >> 4;            // rows 8ty .. 8ty+7
    const int rowbase = blockIdx.x * 64;
    const float* w62 = w + KC * CIN * COUT;

    if (tid < 64) jrow[tid] = g_jc[rowbase + tid];
    __syncthreads();

    u64 acc[8][4];
#pragma unroll
    for (int r = 0; r < 8; r++)
#pragma unroll
        for (int c = 0; c < 4; c++) acc[r][c] = 0ull;

    for (int k0 = 0; k0 < CIN; k0 += KT) {
        if (k0) __syncthreads();
        // fill A (gathered + duplicated): 64 rows x 16 float4
#pragma unroll
        for (int it = 0; it < 8; it++) {
            int idx = tid + it * 128;
            int r = idx & 63, cv = idx >> 6;        // cv: 0..15
            int j = jrow[r];
            float4 v = make_float4(0.f, 0.f, 0.f, 0.f);
            if (j >= 0) v = __ldg((const float4*)(feats + j * CIN + k0) + cv);
            float* d = As + (4 * cv) * 128 + 2 * r;
            *(float2*)(d + 0 * 128) = make_float2(v.x, v.x);
            *(float2*)(d + 1 * 128) = make_float2(v.y, v.y);
            *(float2*)(d + 2 * 128) = make_float2(v.z, v.z);
            *(float2*)(d + 3 * 128) = make_float2(v.w, v.w);
        }
        // fill B: 64 k x 32 float4 (straight copy)
#pragma unroll
        for (int it = 0; it < 16; it++) {
            int idx = tid + it * 128;
            int kk = idx >> 5, cv = idx & 31;
            ((float4*)(Bs + kk * 128))[cv] =
                __ldg((const float4*)(w62 + (k0 + kk) * COUT) + cv);
        }
        __syncthreads();

#pragma unroll 2
        for (int kk = 0; kk < KT; kk++) {
            const float* Ab = As + kk * 128 + 16 * ty;
            const float* Bb = Bs + kk * 128 + 8 * tx;
            ulonglong2 a01 = *(const ulonglong2*)(Ab + 0);
            ulonglong2 a23 = *(const ulonglong2*)(Ab + 4);
            ulonglong2 a45 = *(const ulonglong2*)(Ab + 8);
            ulonglong2 a67 = *(const ulonglong2*)(Ab + 12);
            ulonglong2 b01 = *(const ulonglong2*)(Bb + 0);
            ulonglong2 b23 = *(const ulonglong2*)(Bb + 4);
            u64 ad[8] = {a01.x, a01.y, a23.x, a23.y, a45.x, a45.y, a67.x, a67.y};
            u64 bd[4] = {b01.x, b01.y, b23.x, b23.y};
#pragma unroll
            for (int r = 0; r < 8; r++)
#pragma unroll
                for (int c = 0; c < 4; c++)
                    acc[r][c] = ffma2(ad[r], bd[c], acc[r][c]);
        }
    }

#pragma unroll
    for (int r = 0; r < 8; r++) {
        int row = rowbase + 8 * ty + r;
        float2 p0 = *(float2*)&acc[r][0];
        float2 p1 = *(float2*)&acc[r][1];
        float2 p2 = *(float2*)&acc[r][2];
        float2 p3 = *(float2*)&acc[r][3];
        float4* o = (float4*)(out + row * COUT + 8 * tx);
        o[0] = make_float4(p0.x, p0.y, p1.x, p1.y);
        o[1] = make_float4(p2.x, p2.y, p3.x, p3.y);
    }
}

// ---------------------------------------------------------------------------
// rare non-center contributions: out[i] += feats[j] @ w[k]
__global__ void k_apply(const float* __restrict__ feats,
                        const float* __restrict__ w,
                        float* __restrict__ out) {
    int cnt = g_paircnt;
    if (cnt > MAXP) cnt = MAXP;
    int t = threadIdx.x;   // 128
    for (int p = blockIdx.x; p < cnt; p += gridDim.x) {
        int i = g_pairs[3 * p + 0];
        int k = g_pairs[3 * p + 1];
        int j = g_pairs[3 * p + 2];
        const float* f  = feats + j * CIN;
        const float* wk = w + k * CIN * COUT;
        float acc = 0.0f;
#pragma unroll 8
        for (int c = 0; c < CIN; c++)
            acc += __ldg(f + c) * __ldg(wk + c * COUT + t);
        atomicAdd(out + i * COUT + t, acc);
    }
}

// ---------------------------------------------------------------------------
extern "C" void kernel_launch(void* const* d_in, const int* in_sizes, int n_in,
                              void* d_out, int out_size) {
    const float* feats  = (const float*)d_in[0];
    const float* anchor = (const float*)d_in[1];
    const float* w      = (const float*)d_in[2];
    float* out = (float*)d_out;

    cudaFuncSetAttribute(k_gemm, cudaFuncAttributeMaxDynamicSharedMemorySize,
                         GEMM_SMEM);

    k_clear<<<1250, 256>>>();                       // 320000 threads
    k_insert<<<(NPTS + 255) / 256, 256>>>(anchor);
    k_pairs<<<(NPTS * 32 + 255) / 256, 256>>>();
    k_gemm<<<NPTS / 64, 128, GEMM_SMEM>>>(feats, w, out);
    k_apply<<<128, 128>>>(feats, w, out);
}